// round 6
// baseline (speedup 1.0000x reference)
#include <cuda_runtime.h>
#include <cstdint>

// Embedding gather, bucket-compacted full tiles:
//   x : [16384] int32 token ids        (d_in[0])
//   W : [1024, 50257] f32 row-major    (d_in[1]); embedding of tok = column tok
//   out[s, :] = W[:, x[s]]
//
// Pipeline:
//   k_hist    : histogram tokens by bucket (tok>>6, 786 buckets of 256B)
//   k_scan    : 1-block exclusive scan -> g_off; re-zeroes g_cnt (no zero kernel)
//   k_scatter : compact (tok,pos) grouped by bucket (intra-bucket order free)
//   k_gather  : 512 x 8 blocks, ALWAYS-FULL 32-token tiles. Warp lanes =
//               clustered tokens (<=16 sectors/LDG), smem transpose ->
//               coalesced float4 streaming stores.

#define TOKENS    50257
#define DIMS      1024
#define NTOK      16384
#define BSHIFT    6
#define NBUCKETS  ((TOKENS + 63) / 64)   // 786
#define DIM_CHUNK 128
#define NCHUNKS   (DIMS / DIM_CHUNK)     // 8
#define NTILES    (NTOK / 32)            // 512

__device__ int  g_cnt[NBUCKETS];         // zero at load; re-zeroed by k_scan
__device__ int  g_off[NBUCKETS];         // rebuilt each call
__device__ int2 g_compact[NTOK];         // (tok, original position), bucket-grouped

__global__ void k_hist(const int* __restrict__ x)
{
    int i = blockIdx.x * blockDim.x + threadIdx.x;
    if (i < NTOK) atomicAdd(&g_cnt[__ldg(&x[i]) >> BSHIFT], 1);
}

__global__ __launch_bounds__(1024, 1)
void k_scan()    // NBUCKETS(786) <= 1024: single-pass block scan
{
    __shared__ int buf[1024];
    int tid = threadIdx.x;
    int v = (tid < NBUCKETS) ? g_cnt[tid] : 0;
    buf[tid] = v;
    __syncthreads();
#pragma unroll
    for (int off = 1; off < 1024; off <<= 1) {
        int t = (tid >= off) ? buf[tid - off] : 0;
        __syncthreads();
        buf[tid] += t;
        __syncthreads();
    }
    if (tid < NBUCKETS) {
        g_off[tid] = buf[tid] - v;   // exclusive
        g_cnt[tid] = 0;              // self-reset for next call
    }
}

__global__ void k_scatter(const int* __restrict__ x)
{
    int i = blockIdx.x * blockDim.x + threadIdx.x;
    if (i < NTOK) {
        int tok = __ldg(&x[i]);
        int p = atomicAdd(&g_off[tok >> BSHIFT], 1);
        g_compact[p] = make_int2(tok, i);
    }
}

// grid (512, 8), 128 threads = 4 warps x 32 dims. One full tile per block.
__global__ __launch_bounds__(128, 12)
void k_gather(const float* __restrict__ W, float4* __restrict__ out)
{
    __shared__ float tile[DIM_CHUNK][34];    // pad 34: conflict-free both phases
    __shared__ int s_tok[32], s_pos[32];

    const int tid  = threadIdx.x;
    const int lane = tid & 31;
    const int wd   = (tid >> 5) * 32;        // warp's dim base within chunk

    if (tid < 32) {
        int2 e = g_compact[blockIdx.x * 32 + tid];
        s_tok[tid] = e.x;
        s_pos[tid] = e.y;
    }
    __syncthreads();

    // Phase 1: lanes = clustered tokens; 32 independent strided LDGs/thread.
    {
        const float* base = W + (size_t)(blockIdx.y * DIM_CHUNK + wd) * TOKENS
                              + s_tok[lane];
#pragma unroll
        for (int k = 0; k < 32; k++)
            tile[wd + k][lane] = __ldg(base + (size_t)k * TOKENS);
    }
    __syncthreads();

    // Phase 2: coalesced streaming float4 stores. j = token, 8 f4/thread.
    {
        const int j  = tid >> 2;
        const int f0 = tid & 3;
        const size_t orow = (size_t)s_pos[j] * (DIMS / 4)
                          + blockIdx.y * (DIM_CHUNK / 4);
#pragma unroll
        for (int k = 0; k < 8; k++) {
            int f4i = f0 + k * 4;
            int d = f4i * 4;
            float4 v = make_float4(tile[d][j], tile[d + 1][j],
                                   tile[d + 2][j], tile[d + 3][j]);
            __stwt(&out[orow + f4i], v);
        }
    }
}

extern "C" void kernel_launch(void* const* d_in, const int* in_sizes, int n_in,
                              void* d_out, int out_size)
{
    const int*   x = (const int*)  d_in[0];
    const float* W = (const float*)d_in[1];
    float4*      o = (float4*)     d_out;

    k_hist   <<<(NTOK + 255) / 256, 256>>>(x);
    k_scan   <<<1, 1024>>>();
    k_scatter<<<(NTOK + 255) / 256, 256>>>(x);

    dim3 grid(NTILES, NCHUNKS);              // (512, 8)
    k_gather <<<grid, 128>>>(W, o);
}

// round 7
// speedup vs baseline: 1.1074x; 1.1074x over previous
#include <cuda_runtime.h>
#include <cstdint>

// Embedding gather, compacted + direct-store (2 kernels):
//   x : [16384] int32 token ids        (d_in[0])
//   W : [1024, 50257] f32 row-major    (d_in[1]); embedding of tok = column tok
//   out[s, :] = W[:, x[s]]
//
// k_prep   : ONE block fuses hist -> scan -> scatter over 786 buckets
//            (tok>>6, 256B windows); g_compact = tokens grouped by bucket.
// k_gather : thread = (token lane, 4-dim group). 4 clustered LDGs -> one
//            float4 store straight to the output row. No smem transpose,
//            no phase barriers; L2 write-back merges the 16B row pieces.

#define TOKENS    50257
#define DIMS      1024
#define NTOK      16384
#define BSHIFT    6
#define NBUCKETS  ((TOKENS + 63) / 64)   // 786
#define NTILES    (NTOK / 32)            // 512
#define DIMS_PER_BLOCK 256
#define NCHUNKS   (DIMS / DIMS_PER_BLOCK) // 4

__device__ int2 g_compact[NTOK];          // (tok, original position)

// ---- fused hist + scan + scatter, one block ----
__global__ __launch_bounds__(1024, 1)
void k_prep(const int* __restrict__ x)
{
    __shared__ int cnt[1024];             // covers NBUCKETS=786, scan buffer
    __shared__ int off[NBUCKETS];

    const int tid = threadIdx.x;
    cnt[tid] = 0;
    __syncthreads();

    int toks[16];                         // 16384 = 16 * 1024 exactly
#pragma unroll
    for (int k = 0; k < 16; k++) {
        toks[k] = __ldg(&x[tid + k * 1024]);
        atomicAdd(&cnt[toks[k] >> BSHIFT], 1);
    }
    __syncthreads();

    int v = cnt[tid];
    __syncthreads();
    cnt[tid] = v;
    __syncthreads();
#pragma unroll
    for (int o = 1; o < 1024; o <<= 1) {  // Hillis-Steele inclusive scan
        int t = (tid >= o) ? cnt[tid - o] : 0;
        __syncthreads();
        cnt[tid] += t;
        __syncthreads();
    }
    if (tid < NBUCKETS) off[tid] = cnt[tid] - v;   // exclusive offsets
    __syncthreads();

#pragma unroll
    for (int k = 0; k < 16; k++) {
        int tok = toks[k];
        int p = atomicAdd(&off[tok >> BSHIFT], 1);
        g_compact[p] = make_int2(tok, tid + k * 1024);
    }
}

// ---- gather: grid (512 tiles, 4 chunks), 256 threads = 8 warps ----
// Warp w covers dims [chunk*256 + w*32, +32); lane = compacted token.
__global__ __launch_bounds__(256)
void k_gather(const float* __restrict__ W, float4* __restrict__ out)
{
    __shared__ int s_tok[32], s_pos[32];

    const int tid = threadIdx.x;
    if (tid < 32) {
        int2 e = g_compact[blockIdx.x * 32 + tid];
        s_tok[tid] = e.x;
        s_pos[tid] = e.y;
    }
    __syncthreads();

    const int lane = tid & 31;
    const int dim0 = blockIdx.y * DIMS_PER_BLOCK + (tid >> 5) * 32;

    const float* base = W + (size_t)dim0 * TOKENS + s_tok[lane];
    const size_t orow = (size_t)s_pos[lane] * (DIMS / 4) + (dim0 >> 2);

#pragma unroll
    for (int i = 0; i < 8; i++) {
        // 4 clustered loads: lanes span <=512B of one dim row (<=16 sectors).
        float4 v;
        v.x = __ldg(base + (size_t)(i * 4 + 0) * TOKENS);
        v.y = __ldg(base + (size_t)(i * 4 + 1) * TOKENS);
        v.z = __ldg(base + (size_t)(i * 4 + 2) * TOKENS);
        v.w = __ldg(base + (size_t)(i * 4 + 3) * TOKENS);
        // Thread writes consecutive 16B pieces of its row; L2 merges lines.
        out[orow + i] = v;
    }
}

extern "C" void kernel_launch(void* const* d_in, const int* in_sizes, int n_in,
                              void* d_out, int out_size)
{
    const int*   x = (const int*)  d_in[0];
    const float* W = (const float*)d_in[1];
    float4*      o = (float4*)     d_out;

    k_prep  <<<1, 1024>>>(x);

    dim3 grid(NTILES, NCHUNKS);            // (512, 4)
    k_gather<<<grid, 256>>>(W, o);
}